// round 6
// baseline (speedup 1.0000x reference)
#include <cuda_runtime.h>
#include <math.h>

#define BB   16
#define NNODE 1000
#define EEDGE 4000
#define DDIM 256
#define HHEAD 4
#define HDDIM 1024
#define LSEQ 64
#define AACT 128
#define OHID 256
#define G3   768

// ---------------- scratch (device globals; no allocation allowed) ----------------
__device__ float d_x[BB*NNODE*DDIM];
__device__ float d_eafeat[BB*EEDGE*DDIM];
__device__ float d_q[BB*NNODE*HDDIM];
__device__ float d_kn[BB*NNODE*HDDIM];
__device__ float d_vn[BB*NNODE*HDDIM];
__device__ float d_skip[BB*NNODE*HDDIM];
__device__ float d_ep[BB*EEDGE*HDDIM];
__device__ float d_alpha[BB*EEDGE*HHEAD];
__device__ float d_amax[BB*NNODE*HHEAD];
__device__ float d_denom[BB*NNODE*HHEAD];
__device__ float d_agg[BB*NNODE*HDDIM];
__device__ float d_hbuf[BB*NNODE*HDDIM];
__device__ float d_gr[BB*NNODE*DDIM];
__device__ float d_invemb[BB*LSEQ*DDIM];
__device__ float d_invh[BB*LSEQ*DDIM];
__device__ float d_gx[BB*LSEQ*G3];
__device__ float d_invstate[BB*OHID];
__device__ float d_aaemb[BB*AACT*DDIM];

// ---------------- gathers ----------------
__global__ void gather_rows(float* __restrict__ out, const float* __restrict__ emb,
                            const int* __restrict__ idx) {
    int r = blockIdx.x;
    int t = idx[r];
    const float4* src = (const float4*)(emb + (size_t)t * DDIM);
    float4* dst = (float4*)(out + (size_t)r * DDIM);
    dst[threadIdx.x] = src[threadIdx.x];   // 64 threads * float4 = 256 floats
}

// out[r,:] = emb[tok[r]] + graph_repr[b, node[r], :]
__global__ void mixed_embed(float* __restrict__ out, const float* __restrict__ emb,
                            const int* __restrict__ tok, const int* __restrict__ node,
                            int perB) {
    int r = blockIdx.x;
    int b = r / perB;
    int t = tok[r];
    int nd = node[r];
    const float* e1 = emb + (size_t)t * DDIM;
    const float* e2 = d_gr + (size_t)(b * NNODE + nd) * DDIM;
    int c = threadIdx.x;   // 256 threads
    out[(size_t)r * DDIM + c] = e1[c] + e2[c];
}

// ---------------- tiled fp32 GEMM: C[M,N] = A[M,K] @ W(+bias)(+relu) ----------------
// WT=false: W is [K,N] row-major.  WT=true: W is [N,K] row-major (i.e. C=A@W^T).
template<bool WT>
__global__ void gemm64(const float* __restrict__ A, const float* __restrict__ W,
                       const float* __restrict__ bias, float* __restrict__ C,
                       int M, int Nn, int K, int relu) {
    __shared__ float As[16][68];
    __shared__ float Ws[16][68];
    int tid = threadIdx.x;                 // 256 threads
    int bm = blockIdx.y * 64, bn = blockIdx.x * 64;
    int tm = (tid >> 4) * 4, tn = (tid & 15) * 4;
    float acc[4][4];
#pragma unroll
    for (int i = 0; i < 4; i++)
#pragma unroll
        for (int j = 0; j < 4; j++) acc[i][j] = 0.f;

    int la_m = tid >> 2, la_k = (tid & 3) * 4;
    for (int k0 = 0; k0 < K; k0 += 16) {
        float4 a4 = *(const float4*)&A[(size_t)(bm + la_m) * K + k0 + la_k];
        As[la_k + 0][la_m] = a4.x; As[la_k + 1][la_m] = a4.y;
        As[la_k + 2][la_m] = a4.z; As[la_k + 3][la_m] = a4.w;
        if (!WT) {
            int wk = tid >> 4, wn = (tid & 15) * 4;
            float4 w4 = *(const float4*)&W[(size_t)(k0 + wk) * Nn + bn + wn];
            *(float4*)&Ws[wk][wn] = w4;
        } else {
            int wn = tid >> 2, wk = (tid & 3) * 4;
            float4 w4 = *(const float4*)&W[(size_t)(bn + wn) * K + k0 + wk];
            Ws[wk + 0][wn] = w4.x; Ws[wk + 1][wn] = w4.y;
            Ws[wk + 2][wn] = w4.z; Ws[wk + 3][wn] = w4.w;
        }
        __syncthreads();
#pragma unroll
        for (int kk = 0; kk < 16; kk++) {
            float4 a = *(const float4*)&As[kk][tm];
            float4 w = *(const float4*)&Ws[kk][tn];
            acc[0][0] += a.x * w.x; acc[0][1] += a.x * w.y; acc[0][2] += a.x * w.z; acc[0][3] += a.x * w.w;
            acc[1][0] += a.y * w.x; acc[1][1] += a.y * w.y; acc[1][2] += a.y * w.z; acc[1][3] += a.y * w.w;
            acc[2][0] += a.z * w.x; acc[2][1] += a.z * w.y; acc[2][2] += a.z * w.z; acc[2][3] += a.z * w.w;
            acc[3][0] += a.w * w.x; acc[3][1] += a.w * w.y; acc[3][2] += a.w * w.z; acc[3][3] += a.w * w.w;
        }
        __syncthreads();
    }
#pragma unroll
    for (int i = 0; i < 4; i++) {
#pragma unroll
        for (int j = 0; j < 4; j++) {
            float v = acc[i][j];
            if (bias) v += bias[bn + tn + j];
            if (relu) v = fmaxf(v, 0.f);
            C[(size_t)(bm + tm + i) * Nn + bn + tn + j] = v;
        }
    }
}

// ---------------- attention ----------------
__global__ void alpha_kernel(const int* __restrict__ eidx) {
    int be = blockIdx.x;                      // B*E
    int b = be / EEDGE, e = be - b * EEDGE;
    int src = eidx[(b * 2) * EEDGE + e];
    int dst = eidx[(b * 2 + 1) * EEDGE + e];
    int h = threadIdx.x >> 5, lane = threadIdx.x & 31;
    const float* qp = d_q  + (size_t)(b * NNODE + dst) * HDDIM + h * DDIM;
    const float* kp = d_kn + (size_t)(b * NNODE + src) * HDDIM + h * DDIM;
    const float* ep = d_ep + (size_t)be * HDDIM + h * DDIM;
    float acc = 0.f;
    for (int i = lane; i < DDIM; i += 32) acc += qp[i] * (kp[i] + ep[i]);
#pragma unroll
    for (int o = 16; o > 0; o >>= 1) acc += __shfl_xor_sync(0xffffffffu, acc, o);
    if (lane == 0) d_alpha[(size_t)be * HHEAD + h] = acc * 0.0625f;  // 1/sqrt(256)
}

__global__ void init_bufs() {
    int i = blockIdx.x * blockDim.x + threadIdx.x;
    if (i < BB * NNODE * HDDIM) d_agg[i] = 0.f;
    if (i < BB * NNODE * HHEAD) {
        d_amax[i] = __int_as_float(0xff800000);  // -inf
        d_denom[i] = 0.f;
    }
}

__device__ __forceinline__ void atomicMaxF(float* addr, float val) {
    if (val >= 0.f) atomicMax((int*)addr, __float_as_int(val));
    else atomicMin((unsigned int*)addr, __float_as_uint(val));
}

__global__ void amax_kernel(const int* __restrict__ eidx) {
    int i = blockIdx.x * blockDim.x + threadIdx.x;   // B*E*H
    if (i >= BB * EEDGE * HHEAD) return;
    int h = i & 3; int be = i >> 2;
    int b = be / EEDGE, e = be - b * EEDGE;
    int dst = eidx[(b * 2 + 1) * EEDGE + e];
    atomicMaxF(&d_amax[(b * NNODE + dst) * HHEAD + h], d_alpha[i]);
}

__global__ void exp_kernel(const int* __restrict__ eidx) {
    int i = blockIdx.x * blockDim.x + threadIdx.x;
    if (i >= BB * EEDGE * HHEAD) return;
    int h = i & 3; int be = i >> 2;
    int b = be / EEDGE, e = be - b * EEDGE;
    int dst = eidx[(b * 2 + 1) * EEDGE + e];
    float ex = expf(d_alpha[i] - d_amax[(b * NNODE + dst) * HHEAD + h]);
    d_alpha[i] = ex;
    atomicAdd(&d_denom[(b * NNODE + dst) * HHEAD + h], ex);
}

__global__ void agg_kernel(const int* __restrict__ eidx) {
    int be = blockIdx.x;
    int b = be / EEDGE, e = be - b * EEDGE;
    int src = eidx[(b * 2) * EEDGE + e];
    int dst = eidx[(b * 2 + 1) * EEDGE + e];
    __shared__ float w[HHEAD];
    if (threadIdx.x < HHEAD) {
        int h = threadIdx.x;
        w[h] = d_alpha[(size_t)be * HHEAD + h] / d_denom[(b * NNODE + dst) * HHEAD + h];
    }
    __syncthreads();
    const float* vp = d_vn + (size_t)(b * NNODE + src) * HDDIM;
    const float* ep = d_ep + (size_t)be * HDDIM;
    float* ag = d_agg + (size_t)(b * NNODE + dst) * HDDIM;
    for (int i = threadIdx.x; i < HDDIM; i += blockDim.x)
        atomicAdd(&ag[i], w[i >> 8] * (vp[i] + ep[i]));
}

__global__ void h_relu_kernel() {
    int i = blockIdx.x * blockDim.x + threadIdx.x;
    if (i < BB * NNODE * HDDIM) d_hbuf[i] = fmaxf(d_agg[i] + d_skip[i], 0.f);
}

// ---------------- GRU (one block per batch element) ----------------
__global__ void gru_kernel(const float* __restrict__ Whh, const float* __restrict__ bhh) {
    int b = blockIdx.x;
    __shared__ float hsh[OHID];
    __shared__ float gsh[G3];
    int t = threadIdx.x;        // 768 threads
    if (t < OHID) hsh[t] = 0.f;
    __syncthreads();
    const float4* wr = (const float4*)(Whh + (size_t)t * OHID);
    float bg = bhh[t];
    for (int l = 0; l < LSEQ; l++) {
        float acc = bg;
#pragma unroll 8
        for (int k = 0; k < OHID / 4; k++) {
            float4 w = wr[k];
            acc += w.x * hsh[4 * k] + w.y * hsh[4 * k + 1] + w.z * hsh[4 * k + 2] + w.w * hsh[4 * k + 3];
        }
        gsh[t] = acc;
        __syncthreads();
        if (t < OHID) {
            const float* gx = d_gx + (size_t)(b * LSEQ + l) * G3;
            float r = 1.f / (1.f + expf(-(gx[t] + gsh[t])));
            float z = 1.f / (1.f + expf(-(gx[OHID + t] + gsh[OHID + t])));
            float c = tanhf(gx[2 * OHID + t] + r * gsh[2 * OHID + t]);
            hsh[t] = (1.f - z) * c + z * hsh[t];
        }
        __syncthreads();
    }
    if (t < OHID) d_invstate[b * OHID + t] = hsh[t];
}

// ---------------- final scoring ----------------
__global__ void aa_score(const float* __restrict__ Wap, const float* __restrict__ bap,
                         const float* __restrict__ Wab, const float* __restrict__ bab,
                         const float* __restrict__ mask, float* __restrict__ out) {
    int ba = blockIdx.x;                 // B*A
    int b = ba / AACT;
    __shared__ float ash[DDIM];
    __shared__ float red[DDIM];
    int o = threadIdx.x;                 // 256 threads
    ash[o] = d_aaemb[(size_t)ba * DDIM + o];
    __syncthreads();
    float acc = 0.f;
#pragma unroll 4
    for (int dd = 0; dd < DDIM; dd++) acc += ash[dd] * Wap[(size_t)dd * OHID + o];
    float p = acc + bap[o];
    float val = p * d_invstate[b * OHID + o];
    val += ash[o] * Wab[o];              // Wab is [256,1]
    red[o] = val;
    __syncthreads();
    for (int s = 128; s > 0; s >>= 1) {
        if (o < s) red[o] += red[o + s];
        __syncthreads();
    }
    if (o == 0) {
        float m = fmaxf(logf(mask[ba]), -3.402823466e38f);
        out[ba] = red[0] + bab[0] + m;
    }
}

// ---------------- launch ----------------
extern "C" void kernel_launch(void* const* d_in, const int* in_sizes, int n_in,
                              void* d_out, int out_size) {
    const int* node_tokens = (const int*)d_in[0];
    const int* edge_tokens = (const int*)d_in[1];
    const int* edge_index  = (const int*)d_in[2];
    const int* inv_token   = (const int*)d_in[3];
    const int* inv_node    = (const int*)d_in[4];
    const int* aa_token    = (const int*)d_in[5];
    const int* aa_node     = (const int*)d_in[6];
    const float* action_mask = (const float*)d_in[7];
    const float* emb  = (const float*)d_in[8];
    const float* Wq   = (const float*)d_in[9];
    const float* bq   = (const float*)d_in[10];
    const float* Wk   = (const float*)d_in[11];
    const float* bk   = (const float*)d_in[12];
    const float* Wv   = (const float*)d_in[13];
    const float* bv   = (const float*)d_in[14];
    const float* We   = (const float*)d_in[15];
    const float* Wskip = (const float*)d_in[16];
    const float* bskip = (const float*)d_in[17];
    const float* W1   = (const float*)d_in[18];
    const float* b1   = (const float*)d_in[19];
    const float* Wp   = (const float*)d_in[20];
    const float* bp   = (const float*)d_in[21];
    const float* W_ih = (const float*)d_in[22];
    const float* W_hh = (const float*)d_in[23];
    const float* b_ih = (const float*)d_in[24];
    const float* b_hh = (const float*)d_in[25];
    const float* Wab  = (const float*)d_in[26];
    const float* bab  = (const float*)d_in[27];
    const float* Wap  = (const float*)d_in[28];
    const float* bap  = (const float*)d_in[29];
    float* out = (float*)d_out;

    float* p_x      = nullptr; cudaGetSymbolAddress((void**)&p_x, d_x);
    float* p_ea     = nullptr; cudaGetSymbolAddress((void**)&p_ea, d_eafeat);
    float* p_q      = nullptr; cudaGetSymbolAddress((void**)&p_q, d_q);
    float* p_kn     = nullptr; cudaGetSymbolAddress((void**)&p_kn, d_kn);
    float* p_vn     = nullptr; cudaGetSymbolAddress((void**)&p_vn, d_vn);
    float* p_skip   = nullptr; cudaGetSymbolAddress((void**)&p_skip, d_skip);
    float* p_ep     = nullptr; cudaGetSymbolAddress((void**)&p_ep, d_ep);
    float* p_h      = nullptr; cudaGetSymbolAddress((void**)&p_h, d_hbuf);
    float* p_gr     = nullptr; cudaGetSymbolAddress((void**)&p_gr, d_gr);
    float* p_invemb = nullptr; cudaGetSymbolAddress((void**)&p_invemb, d_invemb);
    float* p_invh   = nullptr; cudaGetSymbolAddress((void**)&p_invh, d_invh);
    float* p_gx     = nullptr; cudaGetSymbolAddress((void**)&p_gx, d_gx);
    float* p_aaemb  = nullptr; cudaGetSymbolAddress((void**)&p_aaemb, d_aaemb);

    // 1. gathers
    gather_rows<<<BB * NNODE, 64>>>(p_x, emb, node_tokens);
    gather_rows<<<BB * EEDGE, 64>>>(p_ea, emb, edge_tokens);

    // 2. node / edge projections
    {
        dim3 g(HDDIM / 64, (BB * NNODE) / 64);
        gemm64<false><<<g, 256>>>(p_x, Wq, bq, p_q, BB * NNODE, HDDIM, DDIM, 0);
        gemm64<false><<<g, 256>>>(p_x, Wk, bk, p_kn, BB * NNODE, HDDIM, DDIM, 0);
        gemm64<false><<<g, 256>>>(p_x, Wv, bv, p_vn, BB * NNODE, HDDIM, DDIM, 0);
        gemm64<false><<<g, 256>>>(p_x, Wskip, bskip, p_skip, BB * NNODE, HDDIM, DDIM, 0);
    }
    {
        dim3 g(HDDIM / 64, (BB * EEDGE) / 64);
        gemm64<false><<<g, 256>>>(p_ea, We, nullptr, p_ep, BB * EEDGE, HDDIM, DDIM, 0);
    }

    // 3. attention
    alpha_kernel<<<BB * EEDGE, 128>>>(edge_index);
    init_bufs<<<(BB * NNODE * HDDIM + 255) / 256, 256>>>();
    {
        int tot = BB * EEDGE * HHEAD;
        amax_kernel<<<(tot + 255) / 256, 256>>>(edge_index);
        exp_kernel<<<(tot + 255) / 256, 256>>>(edge_index);
    }
    agg_kernel<<<BB * EEDGE, 256>>>(edge_index);
    h_relu_kernel<<<(BB * NNODE * HDDIM + 255) / 256, 256>>>();

    // 4. graph representation
    {
        dim3 g(DDIM / 64, (BB * NNODE) / 64);
        gemm64<false><<<g, 256>>>(p_h, W1, b1, p_gr, BB * NNODE, DDIM, HDDIM, 1);
    }

    // 5. invariant path: mixed embed -> proj -> GRU
    mixed_embed<<<BB * LSEQ, 256>>>(p_invemb, emb, inv_token, inv_node, LSEQ);
    {
        dim3 g(DDIM / 64, (BB * LSEQ) / 64);
        gemm64<false><<<g, 256>>>(p_invemb, Wp, bp, p_invh, BB * LSEQ, DDIM, DDIM, 1);
    }
    {
        dim3 g(G3 / 64, (BB * LSEQ) / 64);
        gemm64<true><<<g, 256>>>(p_invh, W_ih, b_ih, p_gx, BB * LSEQ, G3, DDIM, 0);
    }
    gru_kernel<<<BB, G3>>>(W_hh, b_hh);

    // 6. action scoring
    mixed_embed<<<BB * AACT, 256>>>(p_aaemb, emb, aa_token, aa_node, AACT);
    aa_score<<<BB * AACT, 256>>>(Wap, bap, Wab, bab, action_mask, out);
}